// round 15
// baseline (speedup 1.0000x reference)
#include <cuda_runtime.h>
#include <math.h>

#define EPS 1e-5f
#define MAX_BK 32768
typedef unsigned long long u64;

// ---- scratch (device globals) ----
__device__ float4 g_sums[MAX_BK];           // per-bin {sum fx, sum fy, sum_i, sum_j}
__device__ float  g_cnt [MAX_BK];
__device__ float  g_x  [(size_t)5  * MAX_BK];   // feature-major token features [5][BK]
__device__ float  g_t2 [(size_t)MAX_BK * 32];   // token-major layer-2 pre-BN [BK][32]
__device__ float  g_xstat[20];              // Sx(5) + upper-tri Sxx(15)
__device__ float  g_st2[64];                // [0:32) sum, [32:64) sumsq layer-2
__device__ unsigned g_done;                 // pool completion counter (self-resetting)

__device__ __forceinline__ void red_v4(float4* p, float a, float b, float c, float d) {
    asm volatile("red.global.add.v4.f32 [%0], {%1,%2,%3,%4};"
                 :: "l"(p), "f"(a), "f"(b), "f"(c), "f"(d) : "memory");
}
__device__ __forceinline__ void red_f(float* p, float v) {
    asm volatile("red.global.add.f32 [%0], %1;" :: "l"(p), "f"(v) : "memory");
}

// ---- pool + stats (fast path): CTA = 8192 pixels (512 threads);
// last CTA to finish runs the stats phase (deadlock-free, no spinning). ----
#define CHUNK 8192
#define PTHREADS 512
__global__ void pool_priv_k(const int*   __restrict__ labels,
                            const float* __restrict__ fxp,
                            const float* __restrict__ fyp,
                            const int*   __restrict__ fidx,
                            const int*   __restrict__ nfp,
                            int P, int h, int K, int cpb,
                            int BK, float sx, float sy) {
    extern __shared__ char sm[];
    u64* s_ij = (u64*)sm;                       // [K]
    u64* s_xy = (u64*)(sm + (size_t)K * 8);     // [K]
    __shared__ unsigned s_rank;
    int t = threadIdx.x;
    if (blockIdx.x == 0) {
        if (t < 20) g_xstat[t] = 0.f;
        if (t < 64) g_st2[t] = 0.f;
    }
    for (int q = t; q < K; q += PTHREADS) { s_ij[q] = 0ull; s_xy[q] = 0ull; }
    __syncthreads();

    int b     = blockIdx.x / cpb;
    int chunk = blockIdx.x - b * cpb;
    int base4 = (b * P + chunk * CHUNK) >> 2;
#pragma unroll
    for (int it = 0; it < CHUNK / (PTHREADS * 4); it++) {
        int g4 = base4 + it * PTHREADS + t;
        int4   lb = ((const int4*)  labels)[g4];
        float4 vx = ((const float4*)fxp)[g4];
        float4 vy = ((const float4*)fyp)[g4];
        int p0  = g4 << 2;
        int pin = p0 - b * P;
        int i   = pin / h;
        int j   = pin - i * h;              // h % 4 == 0 -> 4-pack same row
        u64 bi = ((u64)i << 40) | 1ull;
        unsigned ax, ay;
        ax = (unsigned)__float2int_rn(fmaf(vx.x, 4096.f, 65536.f));
        ay = (unsigned)__float2int_rn(fmaf(vy.x, 4096.f, 65536.f));
        atomicAdd(&s_xy[lb.x], ((u64)ay << 32) | ax);
        atomicAdd(&s_ij[lb.x], bi | ((u64)(j + 0) << 16));
        ax = (unsigned)__float2int_rn(fmaf(vx.y, 4096.f, 65536.f));
        ay = (unsigned)__float2int_rn(fmaf(vy.y, 4096.f, 65536.f));
        atomicAdd(&s_xy[lb.y], ((u64)ay << 32) | ax);
        atomicAdd(&s_ij[lb.y], bi | ((u64)(j + 1) << 16));
        ax = (unsigned)__float2int_rn(fmaf(vx.z, 4096.f, 65536.f));
        ay = (unsigned)__float2int_rn(fmaf(vy.z, 4096.f, 65536.f));
        atomicAdd(&s_xy[lb.z], ((u64)ay << 32) | ax);
        atomicAdd(&s_ij[lb.z], bi | ((u64)(j + 2) << 16));
        ax = (unsigned)__float2int_rn(fmaf(vx.w, 4096.f, 65536.f));
        ay = (unsigned)__float2int_rn(fmaf(vy.w, 4096.f, 65536.f));
        atomicAdd(&s_xy[lb.w], ((u64)ay << 32) | ax);
        atomicAdd(&s_ij[lb.w], bi | ((u64)(j + 3) << 16));
    }
    __syncthreads();
    for (int q = t; q < K; q += PTHREADS) {
        u64 p = s_ij[q];
        if (p) {
            unsigned c = (unsigned)(p & 0xFFFFull);
            float sj = (float)(unsigned)((p >> 16) & 0xFFFFFFull);
            float si = (float)(unsigned)(p >> 40);
            u64 pxy = s_xy[q];
            long long ix = (long long)(unsigned)(pxy & 0xFFFFFFFFull) - (long long)c * 65536ll;
            long long iy = (long long)(unsigned)(pxy >> 32)           - (long long)c * 65536ll;
            red_v4(&g_sums[b * K + q], (float)ix * (1.f / 4096.f),
                   (float)iy * (1.f / 4096.f), si, sj);
            red_f(&g_cnt[b * K + q], (float)c);
        }
    }

    // ---- completion count; last CTA runs the stats phase ----
    __threadfence();
    __syncthreads();
    if (t == 0) s_rank = atomicAdd(&g_done, 1u);
    __syncthreads();
    if (s_rank != gridDim.x - 1) return;
    __threadfence();                        // acquire: see all CTAs' REDs

    int nf = nfp ? *nfp : 100;
    float invnf = 1.f / (float)(nf - 1);
    float v[20];
#pragma unroll
    for (int q = 0; q < 20; q++) v[q] = 0.f;
    for (int tok = t; tok < BK; tok += PTHREADS) {
        int bb = tok / K;
        float x0 = (float)__ldg(&fidx[bb]) * invnf;
        float cr = g_cnt[tok];
        float ic = 1.f / fmaxf(cr, 1.f);
        float4 s = g_sums[tok];
        float x1 = s.x * ic, x2 = s.y * ic;
        float x3 = (cr > 0.f) ? fmaf(s.z * ic, sx, -1.f) : 0.f;
        float x4 = (cr > 0.f) ? fmaf(s.w * ic, sy, -1.f) : 0.f;
        // re-zero bin for next graph replay (we are the last reader)
        g_sums[tok] = make_float4(0.f, 0.f, 0.f, 0.f);
        g_cnt[tok]  = 0.f;
        g_x[tok]          = x0;
        g_x[BK + tok]     = x1;
        g_x[2 * BK + tok] = x2;
        g_x[3 * BK + tok] = x3;
        g_x[4 * BK + tok] = x4;
        float xv[5] = {x0, x1, x2, x3, x4};
        int ix2 = 0;
#pragma unroll
        for (int d = 0; d < 5; d++) v[ix2++] += xv[d];
#pragma unroll
        for (int d = 0; d < 5; d++)
#pragma unroll
            for (int e = d; e < 5; e++) v[ix2++] += xv[d] * xv[e];
    }
#pragma unroll
    for (int q = 0; q < 20; q++) {
#pragma unroll
        for (int off = 16; off; off >>= 1)
            v[q] += __shfl_xor_sync(0xffffffffu, v[q], off);
    }
    if ((t & 31) == 0) {
#pragma unroll
        for (int q = 0; q < 20; q++) red_f(&g_xstat[q], v[q]);
    }
    if (t == 0) g_done = 0;                 // reset for next graph replay
}

// ---- pool fallback: direct global REDs ----
__global__ void pool_gl_k(const int*   __restrict__ labels,
                          const float* __restrict__ fxp,
                          const float* __restrict__ fyp,
                          int P, int h, int K, int Np) {
    int t = threadIdx.x;
    if (blockIdx.x == 0) {
        if (t < 20) g_xstat[t] = 0.f;
        if (t < 64) g_st2[t] = 0.f;
    }
    int p0 = blockIdx.x * blockDim.x + t;
    if (p0 >= Np) return;
    int b   = p0 / P;
    int pin = p0 - b * P;
    int i   = pin / h;
    int j   = pin - i * h;
    int l   = labels[p0];
    red_v4(&g_sums[b * K + l], fxp[p0], fyp[p0], (float)i, (float)j);
    red_f(&g_cnt[b * K + l], 1.f);
}

// ---- stats (fallback path only): x[5] -> g_x, Sx/Sxx, re-zero bins ----
__global__ void stats_k(const int* __restrict__ fidx,
                        const int* __restrict__ nfp,
                        int K, int BK, float sx, float sy) {
#if __CUDA_ARCH__ >= 900
    cudaGridDependencySynchronize();
#endif
    int tok  = blockIdx.x * 256 + threadIdx.x;
    int lane = threadIdx.x & 31;
    float v[20];
#pragma unroll
    for (int q = 0; q < 20; q++) v[q] = 0.f;
    if (tok < BK) {
        int nf = nfp ? *nfp : 100;
        float invnf = 1.f / (float)(nf - 1);
        int b = tok / K;
        float x0 = (float)__ldg(&fidx[b]) * invnf;
        float cr = g_cnt[tok];
        float ic = 1.f / fmaxf(cr, 1.f);
        float4 s = g_sums[tok];
        float x1 = s.x * ic, x2 = s.y * ic;
        float x3 = (cr > 0.f) ? fmaf(s.z * ic, sx, -1.f) : 0.f;
        float x4 = (cr > 0.f) ? fmaf(s.w * ic, sy, -1.f) : 0.f;
        g_sums[tok] = make_float4(0.f, 0.f, 0.f, 0.f);
        g_cnt[tok]  = 0.f;
        g_x[tok]          = x0;
        g_x[BK + tok]     = x1;
        g_x[2 * BK + tok] = x2;
        g_x[3 * BK + tok] = x3;
        g_x[4 * BK + tok] = x4;
        float xv[5] = {x0, x1, x2, x3, x4};
        int ix = 0;
#pragma unroll
        for (int d = 0; d < 5; d++) v[ix++] = xv[d];
#pragma unroll
        for (int d = 0; d < 5; d++)
#pragma unroll
            for (int e = d; e < 5; e++) v[ix++] = xv[d] * xv[e];
    }
#pragma unroll
    for (int q = 0; q < 20; q++) {
#pragma unroll
        for (int off = 16; off; off >>= 1)
            v[q] += __shfl_xor_sync(0xffffffffu, v[q], off);
    }
    if (lane == 0) {
#pragma unroll
        for (int q = 0; q < 20; q++) red_f(&g_xstat[q], v[q]);
    }
}

// ---- fused mlp1+mlp2: R12 exact (256 thr, thread = token x half, regs uncapped) ----
__global__ void __launch_bounds__(256, 1) mlp12_k(
        const float* __restrict__ cw,   // [64,5]
        const float* __restrict__ cbp,  // [64]
        const float* __restrict__ g1,
        const float* __restrict__ b1,
        const float* __restrict__ lw,   // [32,64]
        const float* __restrict__ lbp,  // [32]
        int BK, float invN) {
    __shared__ float xs[20];
    __shared__ float cw2p[512];
    __shared__ float wsm[2048];
    __shared__ float lbs[32];
    __shared__ float ssum[32], ssq[32];
    __shared__ float tile[8 * 528];

    int t = threadIdx.x, lane = t & 31, w = t >> 5;
    // prologue (independent of predecessor): float4 weight staging
    {
        const float4* lw4 = (const float4*)lw;
        float4* w4s = (float4*)wsm;
        for (int q = t; q < 512; q += 256) w4s[q] = __ldg(&lw4[q]);
    }
    if (t < 32) { lbs[t] = __ldg(&lbp[t]); ssum[t] = 0.f; ssq[t] = 0.f; }
#if __CUDA_ARCH__ >= 900
    cudaGridDependencySynchronize();
#endif
    if (t < 20) xs[t] = g_xstat[t];
    __syncthreads();
    if (t < 64) {
        int ch = t;
        float wv[5];
#pragma unroll
        for (int d = 0; d < 5; d++) wv[d] = __ldg(&cw[ch * 5 + d]);
        float bv = __ldg(&cbp[ch]);
        float m0 = 0.f;
#pragma unroll
        for (int d = 0; d < 5; d++) m0 = fmaf(wv[d], xs[d] * invN, m0);
        float q2 = 0.f; int ix = 5;
#pragma unroll
        for (int d = 0; d < 5; d++)
#pragma unroll
            for (int e = d; e < 5; e++) {
                float S = xs[ix++] * invN;
                q2 = fmaf((d == e ? 1.f : 2.f) * wv[d] * wv[e], S, q2);
            }
        float var = q2 - m0 * m0;
        float sc  = __ldg(&g1[ch]) * rsqrtf(var + EPS);
        float cbf = fmaf(bv, sc, __ldg(&b1[ch]) - (m0 + bv) * sc);
#pragma unroll
        for (int d = 0; d < 5; d++) cw2p[ch * 8 + d] = wv[d] * sc;
        cw2p[ch * 8 + 5] = cbf;
        cw2p[ch * 8 + 6] = 0.f;
        cw2p[ch * 8 + 7] = 0.f;
    }
    __syncthreads();

    int tok = blockIdx.x * 128 + (t >> 1);
    int hf  = t & 1;
    bool act = tok < BK;
    int tclamp = act ? tok : (BK - 1);
    float x0 = g_x[tclamp];
    float x1 = g_x[BK + tclamp];
    float x2 = g_x[2 * BK + tclamp];
    float x3 = g_x[3 * BK + tclamp];
    float x4 = g_x[4 * BK + tclamp];

    float o[16];
#pragma unroll
    for (int c = 0; c < 16; c++) o[c] = lbs[hf * 16 + c];

    const float4* cw4 = (const float4*)cw2p;
    const float4* w4  = (const float4*)wsm;
#pragma unroll
    for (int chunk = 0; chunk < 4; chunk++) {
        float z[16];
#pragma unroll
        for (int c = 0; c < 16; c++) {
            int ch = chunk * 16 + c;
            float4 a = cw4[ch * 2];
            float4 b = cw4[ch * 2 + 1];
            float v = fmaf(a.x, x0, fmaf(a.y, x1, fmaf(a.z, x2,
                      fmaf(a.w, x3, fmaf(b.x, x4, b.y)))));
            z[c] = fmaxf(v, 0.f);
        }
#pragma unroll
        for (int cc = 0; cc < 16; cc++) {
            int row = (hf * 16 + cc) * 16 + chunk * 4;
#pragma unroll
            for (int q = 0; q < 4; q++) {
                float4 ww = w4[row + q];
                o[cc] = fmaf(z[q*4+0], ww.x, fmaf(z[q*4+1], ww.y,
                        fmaf(z[q*4+2], ww.z, fmaf(z[q*4+3], ww.w, o[cc]))));
            }
        }
    }
    if (!act) {
#pragma unroll
        for (int c = 0; c < 16; c++) o[c] = 0.f;
    }
    if (act) {
        float4* dst = (float4*)&g_t2[(size_t)tok * 32 + hf * 16];
#pragma unroll
        for (int q = 0; q < 4; q++)
            dst[q] = make_float4(o[4*q], o[4*q+1], o[4*q+2], o[4*q+3]);
    }

    // BN2 stats: per-warp stride-33 transpose (16 tokens x 32 channels)
    float* tw = tile + w * 528;
    int tokin = (t >> 1) & 15;
#pragma unroll
    for (int c = 0; c < 16; c++)
        tw[tokin * 33 + hf * 16 + c] = o[c];
    __syncwarp();
    float s1 = 0.f, s2 = 0.f;
#pragma unroll
    for (int i = 0; i < 16; i++) {
        float v = tw[i * 33 + lane];
        s1 += v; s2 = fmaf(v, v, s2);
    }
    atomicAdd(&ssum[lane], s1);
    atomicAdd(&ssq[lane], s2);
    __syncthreads();
    if (t < 32) { red_f(&g_st2[t], ssum[t]); red_f(&g_st2[32 + t], ssq[t]); }
}

// ---- mlp3: warp per 8 tokens, lane = channel; butterfly norm ----
__global__ void mlp3_k(const float* __restrict__ g2,
                       const float* __restrict__ b2,
                       float* __restrict__ out,
                       int BK, float invN) {
#if __CUDA_ARCH__ >= 900
    cudaGridDependencySynchronize();
#endif
    __shared__ float sc[32], sh[32];
    int t = threadIdx.x, lane = t & 31, w = t >> 5;
    if (t < 32) {
        float m   = g_st2[t] * invN;
        float var = g_st2[32 + t] * invN - m * m;
        float s   = g2[t] * rsqrtf(var + EPS);
        sc[t] = s; sh[t] = b2[t] - m * s;
    }
    __syncthreads();
    float scl = sc[lane], shl = sh[lane];
    int tok0 = (blockIdx.x * 8 + w) * 8;
    float v[8];
#pragma unroll
    for (int tt = 0; tt < 8; tt++) {
        int tok = tok0 + tt;
        v[tt] = (tok < BK) ? g_t2[(size_t)tok * 32 + lane] : 0.f;
    }
#pragma unroll
    for (int tt = 0; tt < 8; tt++) {
        float x = fmaxf(fmaf(v[tt], scl, shl), 0.f);
        float n = x * x;
#pragma unroll
        for (int off = 16; off; off >>= 1)
            n += __shfl_xor_sync(0xffffffffu, n, off);
        float inv = 1.f / fmaxf(sqrtf(n), 1e-8f);
        int tok = tok0 + tt;
        if (tok < BK) out[(size_t)tok * 32 + lane] = x * inv;
    }
}

// ---- host: PDL-chained launches ----
static void launch_pdl(const void* fn, dim3 grid, dim3 block, void** args) {
    cudaLaunchConfig_t cfg = {};
    cfg.gridDim = grid; cfg.blockDim = block;
    cfg.dynamicSmemBytes = 0; cfg.stream = 0;
    cudaLaunchAttribute at[1];
    at[0].id = cudaLaunchAttributeProgrammaticStreamSerialization;
    at[0].val.programmaticStreamSerializationAllowed = 1;
    cfg.attrs = at; cfg.numAttrs = 1;
    cudaLaunchKernelExC(&cfg, fn, args);
}

extern "C" void kernel_launch(void* const* d_in, const int* in_sizes, int n_in,
                              void* d_out, int out_size) {
    const int*   labels = (const int*)  d_in[0];
    const float* fx     = (const float*)d_in[1];
    const float* fy     = (const float*)d_in[2];
    const int*   fidx   = (const int*)  d_in[3];
    int wi = 4;
    const int* nfp = nullptr;
    if (n_in >= 14) { nfp = (const int*)d_in[4]; wi = 6; }
    const float* cw = (const float*)d_in[wi + 0];
    const float* cb = (const float*)d_in[wi + 1];
    const float* g1 = (const float*)d_in[wi + 2];
    const float* b1 = (const float*)d_in[wi + 3];
    const float* lw = (const float*)d_in[wi + 4];
    const float* lb = (const float*)d_in[wi + 5];
    const float* g2 = (const float*)d_in[wi + 6];
    const float* b2 = (const float*)d_in[wi + 7];

    int B  = in_sizes[3];
    int Np = in_sizes[0];
    int P  = Np / B;
    int BK = out_size / 32;
    int K  = BK / B;
    int hh = (int)(sqrt((double)P) + 0.5);
    int ww = P / hh;
    float sx = 2.f / (float)(ww - 1);
    float sy = 2.f / (float)(hh - 1);
    float invN = 1.f / (float)BK;
    float* outp = (float*)d_out;

    bool fast = (hh * ww == P) && (hh % 4 == 0) && (P % CHUNK == 0) &&
                (K <= 2048) && (hh <= 1024) && (ww <= 1024);
    if (fast) {
        int cpb = P / CHUNK;
        pool_priv_k<<<B * cpb, PTHREADS, (size_t)K * 16>>>(
            labels, fx, fy, fidx, nfp, P, hh, K, cpb, BK, sx, sy);
    } else {
        pool_gl_k<<<(Np + 255) / 256, 256>>>(labels, fx, fy, P, hh, K, Np);
        void* args[] = {(void*)&fidx, (void*)&nfp, (void*)&K, (void*)&BK,
                        (void*)&sx, (void*)&sy};
        launch_pdl((const void*)stats_k, dim3((BK + 255) / 256), dim3(256), args);
    }

    {
        void* args[] = {(void*)&cw, (void*)&cb, (void*)&g1, (void*)&b1,
                        (void*)&lw, (void*)&lb, (void*)&BK, (void*)&invN};
        launch_pdl((const void*)mlp12_k, dim3((BK + 127) / 128), dim3(256), args);
    }
    {
        void* args[] = {(void*)&g2, (void*)&b2, (void*)&outp, (void*)&BK, (void*)&invN};
        launch_pdl((const void*)mlp3_k, dim3((BK + 63) / 64), dim3(256), args);
    }
}

// round 16
// speedup vs baseline: 1.3663x; 1.3663x over previous
#include <cuda_runtime.h>
#include <math.h>

#define EPS 1e-5f
#define MAX_BK 32768
typedef unsigned long long u64;

// ---- scratch (device globals) ----
__device__ float4 g_sums[MAX_BK];           // per-bin {sum fx, sum fy, sum_i, sum_j}
__device__ float  g_cnt [MAX_BK];
__device__ float  g_x  [(size_t)5  * MAX_BK];   // feature-major token features [5][BK]
__device__ float  g_t2 [(size_t)MAX_BK * 32];   // token-major layer-2 pre-BN [BK][32]
__device__ float  g_xstat[20];              // Sx(5) + upper-tri Sxx(15)
__device__ float  g_st2[64];                // [0:32) sum, [32:64) sumsq layer-2

__device__ __forceinline__ void red_v4(float4* p, float a, float b, float c, float d) {
    asm volatile("red.global.add.v4.f32 [%0], {%1,%2,%3,%4};"
                 :: "l"(p), "f"(a), "f"(b), "f"(c), "f"(d) : "memory");
}
__device__ __forceinline__ void red_f(float* p, float v) {
    asm volatile("red.global.add.f32 [%0], %1;" :: "l"(p), "f"(v) : "memory");
}

// ---- pool (fast path): CTA = 8192 pixels (512 threads), 2 packed u64 atomics/pixel ----
#define CHUNK 8192
#define PTHREADS 512
__global__ void pool_priv_k(const int*   __restrict__ labels,
                            const float* __restrict__ fxp,
                            const float* __restrict__ fyp,
                            int P, int h, int K, int cpb) {
    extern __shared__ char sm[];
    u64* s_ij = (u64*)sm;                       // [K]
    u64* s_xy = (u64*)(sm + (size_t)K * 8);     // [K]
    int t = threadIdx.x;
    if (blockIdx.x == 0) {
        if (t < 20) g_xstat[t] = 0.f;
        if (t < 64) g_st2[t] = 0.f;
    }
    for (int q = t; q < K; q += PTHREADS) { s_ij[q] = 0ull; s_xy[q] = 0ull; }
    __syncthreads();

    int b     = blockIdx.x / cpb;
    int chunk = blockIdx.x - b * cpb;
    int base4 = (b * P + chunk * CHUNK) >> 2;
#pragma unroll
    for (int it = 0; it < CHUNK / (PTHREADS * 4); it++) {
        int g4 = base4 + it * PTHREADS + t;
        int4   lb = ((const int4*)  labels)[g4];
        float4 vx = ((const float4*)fxp)[g4];
        float4 vy = ((const float4*)fyp)[g4];
        int p0  = g4 << 2;
        int pin = p0 - b * P;
        int i   = pin / h;
        int j   = pin - i * h;              // h % 4 == 0 -> 4-pack same row
        u64 bi = ((u64)i << 40) | 1ull;
        unsigned ax, ay;
        ax = (unsigned)__float2int_rn(fmaf(vx.x, 4096.f, 65536.f));
        ay = (unsigned)__float2int_rn(fmaf(vy.x, 4096.f, 65536.f));
        atomicAdd(&s_xy[lb.x], ((u64)ay << 32) | ax);
        atomicAdd(&s_ij[lb.x], bi | ((u64)(j + 0) << 16));
        ax = (unsigned)__float2int_rn(fmaf(vx.y, 4096.f, 65536.f));
        ay = (unsigned)__float2int_rn(fmaf(vy.y, 4096.f, 65536.f));
        atomicAdd(&s_xy[lb.y], ((u64)ay << 32) | ax);
        atomicAdd(&s_ij[lb.y], bi | ((u64)(j + 1) << 16));
        ax = (unsigned)__float2int_rn(fmaf(vx.z, 4096.f, 65536.f));
        ay = (unsigned)__float2int_rn(fmaf(vy.z, 4096.f, 65536.f));
        atomicAdd(&s_xy[lb.z], ((u64)ay << 32) | ax);
        atomicAdd(&s_ij[lb.z], bi | ((u64)(j + 2) << 16));
        ax = (unsigned)__float2int_rn(fmaf(vx.w, 4096.f, 65536.f));
        ay = (unsigned)__float2int_rn(fmaf(vy.w, 4096.f, 65536.f));
        atomicAdd(&s_xy[lb.w], ((u64)ay << 32) | ax);
        atomicAdd(&s_ij[lb.w], bi | ((u64)(j + 3) << 16));
    }
    __syncthreads();
    for (int q = t; q < K; q += PTHREADS) {
        u64 p = s_ij[q];
        if (p) {
            unsigned c = (unsigned)(p & 0xFFFFull);
            float sj = (float)(unsigned)((p >> 16) & 0xFFFFFFull);
            float si = (float)(unsigned)(p >> 40);
            u64 pxy = s_xy[q];
            long long ix = (long long)(unsigned)(pxy & 0xFFFFFFFFull) - (long long)c * 65536ll;
            long long iy = (long long)(unsigned)(pxy >> 32)           - (long long)c * 65536ll;
            red_v4(&g_sums[b * K + q], (float)ix * (1.f / 4096.f),
                   (float)iy * (1.f / 4096.f), si, sj);
            red_f(&g_cnt[b * K + q], (float)c);
        }
    }
}

// ---- pool fallback: direct global REDs ----
__global__ void pool_gl_k(const int*   __restrict__ labels,
                          const float* __restrict__ fxp,
                          const float* __restrict__ fyp,
                          int P, int h, int K, int Np) {
    int t = threadIdx.x;
    if (blockIdx.x == 0) {
        if (t < 20) g_xstat[t] = 0.f;
        if (t < 64) g_st2[t] = 0.f;
    }
    int p0 = blockIdx.x * blockDim.x + t;
    if (p0 >= Np) return;
    int b   = p0 / P;
    int pin = p0 - b * P;
    int i   = pin / h;
    int j   = pin - i * h;
    int l   = labels[p0];
    red_v4(&g_sums[b * K + l], fxp[p0], fyp[p0], (float)i, (float)j);
    red_f(&g_cnt[b * K + l], 1.f);
}

// ---- stats: x[5] -> g_x, accumulate Sx/Sxx; re-zero pool bins (last reader) ----
__global__ void stats_k(const int* __restrict__ fidx,
                        const int* __restrict__ nfp,
                        int K, int BK, float sx, float sy) {
#if __CUDA_ARCH__ >= 900
    cudaGridDependencySynchronize();
#endif
    int tok  = blockIdx.x * 256 + threadIdx.x;
    int lane = threadIdx.x & 31;
    float v[20];
#pragma unroll
    for (int q = 0; q < 20; q++) v[q] = 0.f;
    if (tok < BK) {
        int nf = nfp ? *nfp : 100;
        float invnf = 1.f / (float)(nf - 1);
        int b = tok / K;
        float x0 = (float)__ldg(&fidx[b]) * invnf;
        float cr = g_cnt[tok];
        float ic = 1.f / fmaxf(cr, 1.f);
        float4 s = g_sums[tok];
        float x1 = s.x * ic, x2 = s.y * ic;
        float x3 = (cr > 0.f) ? fmaf(s.z * ic, sx, -1.f) : 0.f;
        float x4 = (cr > 0.f) ? fmaf(s.w * ic, sy, -1.f) : 0.f;
        // re-zero this bin for the next chain invocation (we are the last reader)
        g_sums[tok] = make_float4(0.f, 0.f, 0.f, 0.f);
        g_cnt[tok]  = 0.f;
        g_x[tok]          = x0;
        g_x[BK + tok]     = x1;
        g_x[2 * BK + tok] = x2;
        g_x[3 * BK + tok] = x3;
        g_x[4 * BK + tok] = x4;
        float xv[5] = {x0, x1, x2, x3, x4};
        int ix = 0;
#pragma unroll
        for (int d = 0; d < 5; d++) v[ix++] = xv[d];
#pragma unroll
        for (int d = 0; d < 5; d++)
#pragma unroll
            for (int e = d; e < 5; e++) v[ix++] = xv[d] * xv[e];
    }
#pragma unroll
    for (int q = 0; q < 20; q++) {
#pragma unroll
        for (int off = 16; off; off >>= 1)
            v[q] += __shfl_xor_sync(0xffffffffu, v[q], off);
    }
    if (lane == 0) {
#pragma unroll
        for (int q = 0; q < 20; q++) red_f(&g_xstat[q], v[q]);
    }
}

// ---- fused mlp1+mlp2: half-split (thread = token x half), 256-thread blocks,
// register budget uncapped (min-blocks 1) so ptxas can pipeline across chunks.
__global__ void __launch_bounds__(256, 1) mlp12_k(
        const float* __restrict__ cw,   // [64,5]
        const float* __restrict__ cbp,  // [64]
        const float* __restrict__ g1,
        const float* __restrict__ b1,
        const float* __restrict__ lw,   // [32,64]
        const float* __restrict__ lbp,  // [32]
        int BK, float invN) {
    __shared__ float xs[20];
    __shared__ float cw2p[512];
    __shared__ float wsm[2048];
    __shared__ float lbs[32];
    __shared__ float ssum[32], ssq[32];
    __shared__ float tile[8 * 528];

    int t = threadIdx.x, lane = t & 31, w = t >> 5;
    // prologue (independent of predecessor): float4 weight staging
    {
        const float4* lw4 = (const float4*)lw;
        float4* w4s = (float4*)wsm;
        for (int q = t; q < 512; q += 256) w4s[q] = __ldg(&lw4[q]);
    }
    if (t < 32) { lbs[t] = __ldg(&lbp[t]); ssum[t] = 0.f; ssq[t] = 0.f; }
#if __CUDA_ARCH__ >= 900
    cudaGridDependencySynchronize();
#endif
    if (t < 20) xs[t] = g_xstat[t];
    __syncthreads();
    if (t < 64) {
        int ch = t;
        float wv[5];
#pragma unroll
        for (int d = 0; d < 5; d++) wv[d] = __ldg(&cw[ch * 5 + d]);
        float bv = __ldg(&cbp[ch]);
        float m0 = 0.f;
#pragma unroll
        for (int d = 0; d < 5; d++) m0 = fmaf(wv[d], xs[d] * invN, m0);
        float q2 = 0.f; int ix = 5;
#pragma unroll
        for (int d = 0; d < 5; d++)
#pragma unroll
            for (int e = d; e < 5; e++) {
                float S = xs[ix++] * invN;
                q2 = fmaf((d == e ? 1.f : 2.f) * wv[d] * wv[e], S, q2);
            }
        float var = q2 - m0 * m0;
        float sc  = __ldg(&g1[ch]) * rsqrtf(var + EPS);
        float cbf = fmaf(bv, sc, __ldg(&b1[ch]) - (m0 + bv) * sc);
#pragma unroll
        for (int d = 0; d < 5; d++) cw2p[ch * 8 + d] = wv[d] * sc;
        cw2p[ch * 8 + 5] = cbf;
        cw2p[ch * 8 + 6] = 0.f;
        cw2p[ch * 8 + 7] = 0.f;
    }
    __syncthreads();

    int tok = blockIdx.x * 128 + (t >> 1);
    int hf  = t & 1;
    bool act = tok < BK;
    int tclamp = act ? tok : (BK - 1);
    float x0 = g_x[tclamp];
    float x1 = g_x[BK + tclamp];
    float x2 = g_x[2 * BK + tclamp];
    float x3 = g_x[3 * BK + tclamp];
    float x4 = g_x[4 * BK + tclamp];

    float o[16];
#pragma unroll
    for (int c = 0; c < 16; c++) o[c] = lbs[hf * 16 + c];

    const float4* cw4 = (const float4*)cw2p;
    const float4* w4  = (const float4*)wsm;
#pragma unroll
    for (int chunk = 0; chunk < 4; chunk++) {
        float z[16];
#pragma unroll
        for (int c = 0; c < 16; c++) {
            int ch = chunk * 16 + c;
            float4 a = cw4[ch * 2];
            float4 b = cw4[ch * 2 + 1];
            float v = fmaf(a.x, x0, fmaf(a.y, x1, fmaf(a.z, x2,
                      fmaf(a.w, x3, fmaf(b.x, x4, b.y)))));
            z[c] = fmaxf(v, 0.f);
        }
#pragma unroll
        for (int cc = 0; cc < 16; cc++) {
            int row = (hf * 16 + cc) * 16 + chunk * 4;
#pragma unroll
            for (int q = 0; q < 4; q++) {
                float4 ww = w4[row + q];
                o[cc] = fmaf(z[q*4+0], ww.x, fmaf(z[q*4+1], ww.y,
                        fmaf(z[q*4+2], ww.z, fmaf(z[q*4+3], ww.w, o[cc]))));
            }
        }
    }
    if (!act) {
#pragma unroll
        for (int c = 0; c < 16; c++) o[c] = 0.f;
    }
    if (act) {
        float4* dst = (float4*)&g_t2[(size_t)tok * 32 + hf * 16];
#pragma unroll
        for (int q = 0; q < 4; q++)
            dst[q] = make_float4(o[4*q], o[4*q+1], o[4*q+2], o[4*q+3]);
    }

    // BN2 stats: per-warp stride-33 transpose (16 tokens x 32 channels)
    float* tw = tile + w * 528;
    int tokin = (t >> 1) & 15;
#pragma unroll
    for (int c = 0; c < 16; c++)
        tw[tokin * 33 + hf * 16 + c] = o[c];
    __syncwarp();
    float s1 = 0.f, s2 = 0.f;
#pragma unroll
    for (int i = 0; i < 16; i++) {
        float v = tw[i * 33 + lane];
        s1 += v; s2 = fmaf(v, v, s2);
    }
    atomicAdd(&ssum[lane], s1);
    atomicAdd(&ssq[lane], s2);
    __syncthreads();
    if (t < 32) { red_f(&g_st2[t], ssum[t]); red_f(&g_st2[32 + t], ssq[t]); }
}

// ---- mlp3: warp per 8 tokens, lane = channel; butterfly norm ----
__global__ void mlp3_k(const float* __restrict__ g2,
                       const float* __restrict__ b2,
                       float* __restrict__ out,
                       int BK, float invN) {
#if __CUDA_ARCH__ >= 900
    cudaGridDependencySynchronize();
#endif
    __shared__ float sc[32], sh[32];
    int t = threadIdx.x, lane = t & 31, w = t >> 5;
    if (t < 32) {
        float m   = g_st2[t] * invN;
        float var = g_st2[32 + t] * invN - m * m;
        float s   = g2[t] * rsqrtf(var + EPS);
        sc[t] = s; sh[t] = b2[t] - m * s;
    }
    __syncthreads();
    float scl = sc[lane], shl = sh[lane];
    int tok0 = (blockIdx.x * 8 + w) * 8;
    float v[8];
#pragma unroll
    for (int tt = 0; tt < 8; tt++) {
        int tok = tok0 + tt;
        v[tt] = (tok < BK) ? g_t2[(size_t)tok * 32 + lane] : 0.f;
    }
#pragma unroll
    for (int tt = 0; tt < 8; tt++) {
        float x = fmaxf(fmaf(v[tt], scl, shl), 0.f);
        float n = x * x;
#pragma unroll
        for (int off = 16; off; off >>= 1)
            n += __shfl_xor_sync(0xffffffffu, n, off);
        float inv = 1.f / fmaxf(sqrtf(n), 1e-8f);
        int tok = tok0 + tt;
        if (tok < BK) out[(size_t)tok * 32 + lane] = x * inv;
    }
}

// ---- host: PDL-chained launches ----
static void launch_pdl(const void* fn, dim3 grid, dim3 block, void** args) {
    cudaLaunchConfig_t cfg = {};
    cfg.gridDim = grid; cfg.blockDim = block;
    cfg.dynamicSmemBytes = 0; cfg.stream = 0;
    cudaLaunchAttribute at[1];
    at[0].id = cudaLaunchAttributeProgrammaticStreamSerialization;
    at[0].val.programmaticStreamSerializationAllowed = 1;
    cfg.attrs = at; cfg.numAttrs = 1;
    cudaLaunchKernelExC(&cfg, fn, args);
}

extern "C" void kernel_launch(void* const* d_in, const int* in_sizes, int n_in,
                              void* d_out, int out_size) {
    const int*   labels = (const int*)  d_in[0];
    const float* fx     = (const float*)d_in[1];
    const float* fy     = (const float*)d_in[2];
    const int*   fidx   = (const int*)  d_in[3];
    int wi = 4;
    const int* nfp = nullptr;
    if (n_in >= 14) { nfp = (const int*)d_in[4]; wi = 6; }
    const float* cw = (const float*)d_in[wi + 0];
    const float* cb = (const float*)d_in[wi + 1];
    const float* g1 = (const float*)d_in[wi + 2];
    const float* b1 = (const float*)d_in[wi + 3];
    const float* lw = (const float*)d_in[wi + 4];
    const float* lb = (const float*)d_in[wi + 5];
    const float* g2 = (const float*)d_in[wi + 6];
    const float* b2 = (const float*)d_in[wi + 7];

    int B  = in_sizes[3];
    int Np = in_sizes[0];
    int P  = Np / B;
    int BK = out_size / 32;
    int K  = BK / B;
    int hh = (int)(sqrt((double)P) + 0.5);
    int ww = P / hh;
    float sx = 2.f / (float)(ww - 1);
    float sy = 2.f / (float)(hh - 1);
    float invN = 1.f / (float)BK;
    float* outp = (float*)d_out;

    bool fast = (hh * ww == P) && (hh % 4 == 0) && (P % CHUNK == 0) &&
                (K <= 2048) && (hh <= 1024) && (ww <= 1024);
    if (fast) {
        int cpb = P / CHUNK;
        pool_priv_k<<<B * cpb, PTHREADS, (size_t)K * 16>>>(labels, fx, fy, P, hh, K, cpb);
    } else {
        pool_gl_k<<<(Np + 255) / 256, 256>>>(labels, fx, fy, P, hh, K, Np);
    }

    {
        void* args[] = {(void*)&fidx, (void*)&nfp, (void*)&K, (void*)&BK,
                        (void*)&sx, (void*)&sy};
        launch_pdl((const void*)stats_k, dim3((BK + 255) / 256), dim3(256), args);
    }
    {
        void* args[] = {(void*)&cw, (void*)&cb, (void*)&g1, (void*)&b1,
                        (void*)&lw, (void*)&lb, (void*)&BK, (void*)&invN};
        launch_pdl((const void*)mlp12_k, dim3((BK + 127) / 128), dim3(256), args);
    }
    {
        void* args[] = {(void*)&g2, (void*)&b2, (void*)&outp, (void*)&BK, (void*)&invN};
        launch_pdl((const void*)mlp3_k, dim3((BK + 63) / 64), dim3(256), args);
    }
}

// round 17
// speedup vs baseline: 1.3728x; 1.0048x over previous
#include <cuda_runtime.h>
#include <math.h>

#define EPS 1e-5f
#define MAX_BK 32768
typedef unsigned long long u64;

// ---- scratch (device globals) ----
__device__ float4 g_sums[MAX_BK];           // per-bin {sum fx, sum fy, sum_i, sum_j}
__device__ float  g_cnt [MAX_BK];
__device__ float  g_x  [(size_t)5  * MAX_BK];   // feature-major token features [5][BK]
__device__ float  g_t2 [(size_t)MAX_BK * 32];   // token-major layer-2 pre-BN [BK][32]
__device__ float  g_xstat[20];              // Sx(5) + upper-tri Sxx(15)
__device__ float  g_st2[64];                // [0:32) sum, [32:64) sumsq layer-2

__device__ __forceinline__ void red_v4(float4* p, float a, float b, float c, float d) {
    asm volatile("red.global.add.v4.f32 [%0], {%1,%2,%3,%4};"
                 :: "l"(p), "f"(a), "f"(b), "f"(c), "f"(d) : "memory");
}
__device__ __forceinline__ void red_f(float* p, float v) {
    asm volatile("red.global.add.f32 [%0], %1;" :: "l"(p), "f"(v) : "memory");
}

// ---- pool (fast path): CTA = 8192 pixels (512 threads), 2 packed u64 atomics/pixel ----
#define CHUNK 8192
#define PTHREADS 512
__global__ void pool_priv_k(const int*   __restrict__ labels,
                            const float* __restrict__ fxp,
                            const float* __restrict__ fyp,
                            int P, int h, int K, int cpb) {
    extern __shared__ char sm[];
    u64* s_ij = (u64*)sm;                       // [K]
    u64* s_xy = (u64*)(sm + (size_t)K * 8);     // [K]
    int t = threadIdx.x;
    if (blockIdx.x == 0) {
        if (t < 20) g_xstat[t] = 0.f;
        if (t < 64) g_st2[t] = 0.f;
    }
    for (int q = t; q < K; q += PTHREADS) { s_ij[q] = 0ull; s_xy[q] = 0ull; }
    __syncthreads();

    int b     = blockIdx.x / cpb;
    int chunk = blockIdx.x - b * cpb;
    int base4 = (b * P + chunk * CHUNK) >> 2;
#pragma unroll
    for (int it = 0; it < CHUNK / (PTHREADS * 4); it++) {
        int g4 = base4 + it * PTHREADS + t;
        int4   lb = ((const int4*)  labels)[g4];
        float4 vx = ((const float4*)fxp)[g4];
        float4 vy = ((const float4*)fyp)[g4];
        int p0  = g4 << 2;
        int pin = p0 - b * P;
        int i   = pin / h;
        int j   = pin - i * h;              // h % 4 == 0 -> 4-pack same row
        u64 bi = ((u64)i << 40) | 1ull;
        unsigned ax, ay;
        ax = (unsigned)__float2int_rn(fmaf(vx.x, 4096.f, 65536.f));
        ay = (unsigned)__float2int_rn(fmaf(vy.x, 4096.f, 65536.f));
        atomicAdd(&s_xy[lb.x], ((u64)ay << 32) | ax);
        atomicAdd(&s_ij[lb.x], bi | ((u64)(j + 0) << 16));
        ax = (unsigned)__float2int_rn(fmaf(vx.y, 4096.f, 65536.f));
        ay = (unsigned)__float2int_rn(fmaf(vy.y, 4096.f, 65536.f));
        atomicAdd(&s_xy[lb.y], ((u64)ay << 32) | ax);
        atomicAdd(&s_ij[lb.y], bi | ((u64)(j + 1) << 16));
        ax = (unsigned)__float2int_rn(fmaf(vx.z, 4096.f, 65536.f));
        ay = (unsigned)__float2int_rn(fmaf(vy.z, 4096.f, 65536.f));
        atomicAdd(&s_xy[lb.z], ((u64)ay << 32) | ax);
        atomicAdd(&s_ij[lb.z], bi | ((u64)(j + 2) << 16));
        ax = (unsigned)__float2int_rn(fmaf(vx.w, 4096.f, 65536.f));
        ay = (unsigned)__float2int_rn(fmaf(vy.w, 4096.f, 65536.f));
        atomicAdd(&s_xy[lb.w], ((u64)ay << 32) | ax);
        atomicAdd(&s_ij[lb.w], bi | ((u64)(j + 3) << 16));
    }
    __syncthreads();
    for (int q = t; q < K; q += PTHREADS) {
        u64 p = s_ij[q];
        if (p) {
            unsigned c = (unsigned)(p & 0xFFFFull);
            float sj = (float)(unsigned)((p >> 16) & 0xFFFFFFull);
            float si = (float)(unsigned)(p >> 40);
            u64 pxy = s_xy[q];
            long long ix = (long long)(unsigned)(pxy & 0xFFFFFFFFull) - (long long)c * 65536ll;
            long long iy = (long long)(unsigned)(pxy >> 32)           - (long long)c * 65536ll;
            red_v4(&g_sums[b * K + q], (float)ix * (1.f / 4096.f),
                   (float)iy * (1.f / 4096.f), si, sj);
            red_f(&g_cnt[b * K + q], (float)c);
        }
    }
}

// ---- pool fallback: direct global REDs ----
__global__ void pool_gl_k(const int*   __restrict__ labels,
                          const float* __restrict__ fxp,
                          const float* __restrict__ fyp,
                          int P, int h, int K, int Np) {
    int t = threadIdx.x;
    if (blockIdx.x == 0) {
        if (t < 20) g_xstat[t] = 0.f;
        if (t < 64) g_st2[t] = 0.f;
    }
    int p0 = blockIdx.x * blockDim.x + t;
    if (p0 >= Np) return;
    int b   = p0 / P;
    int pin = p0 - b * P;
    int i   = pin / h;
    int j   = pin - i * h;
    int l   = labels[p0];
    red_v4(&g_sums[b * K + l], fxp[p0], fyp[p0], (float)i, (float)j);
    red_f(&g_cnt[b * K + l], 1.f);
}

// ---- stats: x[5] -> g_x, accumulate Sx/Sxx; re-zero pool bins (last reader).
// 128 threads x (BK/128) blocks for wider SM spread. ----
__global__ void stats_k(const int* __restrict__ fidx,
                        const int* __restrict__ nfp,
                        int K, int BK, float sx, float sy) {
#if __CUDA_ARCH__ >= 900
    cudaGridDependencySynchronize();
#endif
    int tok  = blockIdx.x * 128 + threadIdx.x;
    int lane = threadIdx.x & 31;
    float v[20];
#pragma unroll
    for (int q = 0; q < 20; q++) v[q] = 0.f;
    if (tok < BK) {
        int nf = nfp ? *nfp : 100;
        float invnf = 1.f / (float)(nf - 1);
        int b = tok / K;
        float x0 = (float)__ldg(&fidx[b]) * invnf;
        float cr = g_cnt[tok];
        float ic = 1.f / fmaxf(cr, 1.f);
        float4 s = g_sums[tok];
        float x1 = s.x * ic, x2 = s.y * ic;
        float x3 = (cr > 0.f) ? fmaf(s.z * ic, sx, -1.f) : 0.f;
        float x4 = (cr > 0.f) ? fmaf(s.w * ic, sy, -1.f) : 0.f;
        // re-zero this bin for the next chain invocation (we are the last reader)
        g_sums[tok] = make_float4(0.f, 0.f, 0.f, 0.f);
        g_cnt[tok]  = 0.f;
        g_x[tok]          = x0;
        g_x[BK + tok]     = x1;
        g_x[2 * BK + tok] = x2;
        g_x[3 * BK + tok] = x3;
        g_x[4 * BK + tok] = x4;
        float xv[5] = {x0, x1, x2, x3, x4};
        int ix = 0;
#pragma unroll
        for (int d = 0; d < 5; d++) v[ix++] = xv[d];
#pragma unroll
        for (int d = 0; d < 5; d++)
#pragma unroll
            for (int e = d; e < 5; e++) v[ix++] = xv[d] * xv[e];
    }
#pragma unroll
    for (int q = 0; q < 20; q++) {
#pragma unroll
        for (int off = 16; off; off >>= 1)
            v[q] += __shfl_xor_sync(0xffffffffu, v[q], off);
    }
    if (lane == 0) {
#pragma unroll
        for (int q = 0; q < 20; q++) red_f(&g_xstat[q], v[q]);
    }
}

// ---- fused mlp1+mlp2: half-split inner loop (R12 exact), 128 threads/CTA,
// 256 CTAs (full chip), register budget uncapped (min-blocks 1). ----
__global__ void __launch_bounds__(128, 1) mlp12_k(
        const float* __restrict__ cw,   // [64,5]
        const float* __restrict__ cbp,  // [64]
        const float* __restrict__ g1,
        const float* __restrict__ b1,
        const float* __restrict__ lw,   // [32,64]
        const float* __restrict__ lbp,  // [32]
        int BK, float invN) {
    __shared__ float xs[20];
    __shared__ float cw2p[512];
    __shared__ float wsm[2048];
    __shared__ float lbs[32];
    __shared__ float ssum[32], ssq[32];
    __shared__ float tile[4 * 528];

    int t = threadIdx.x, lane = t & 31, w = t >> 5;
    // prologue (independent of predecessor): float4 weight staging
    {
        const float4* lw4 = (const float4*)lw;
        float4* w4s = (float4*)wsm;
        for (int q = t; q < 512; q += 128) w4s[q] = __ldg(&lw4[q]);
    }
    if (t < 32) { lbs[t] = __ldg(&lbp[t]); ssum[t] = 0.f; ssq[t] = 0.f; }
#if __CUDA_ARCH__ >= 900
    cudaGridDependencySynchronize();
#endif
    if (t < 20) xs[t] = g_xstat[t];
    __syncthreads();
    if (t < 64) {
        int ch = t;
        float wv[5];
#pragma unroll
        for (int d = 0; d < 5; d++) wv[d] = __ldg(&cw[ch * 5 + d]);
        float bv = __ldg(&cbp[ch]);
        float m0 = 0.f;
#pragma unroll
        for (int d = 0; d < 5; d++) m0 = fmaf(wv[d], xs[d] * invN, m0);
        float q2 = 0.f; int ix = 5;
#pragma unroll
        for (int d = 0; d < 5; d++)
#pragma unroll
            for (int e = d; e < 5; e++) {
                float S = xs[ix++] * invN;
                q2 = fmaf((d == e ? 1.f : 2.f) * wv[d] * wv[e], S, q2);
            }
        float var = q2 - m0 * m0;
        float sc  = __ldg(&g1[ch]) * rsqrtf(var + EPS);
        float cbf = fmaf(bv, sc, __ldg(&b1[ch]) - (m0 + bv) * sc);
#pragma unroll
        for (int d = 0; d < 5; d++) cw2p[ch * 8 + d] = wv[d] * sc;
        cw2p[ch * 8 + 5] = cbf;
        cw2p[ch * 8 + 6] = 0.f;
        cw2p[ch * 8 + 7] = 0.f;
    }
    __syncthreads();

    int tok = blockIdx.x * 64 + (t >> 1);
    int hf  = t & 1;
    bool act = tok < BK;
    int tclamp = act ? tok : (BK - 1);
    float x0 = g_x[tclamp];
    float x1 = g_x[BK + tclamp];
    float x2 = g_x[2 * BK + tclamp];
    float x3 = g_x[3 * BK + tclamp];
    float x4 = g_x[4 * BK + tclamp];

    float o[16];
#pragma unroll
    for (int c = 0; c < 16; c++) o[c] = lbs[hf * 16 + c];

    const float4* cw4 = (const float4*)cw2p;
    const float4* w4  = (const float4*)wsm;
#pragma unroll
    for (int chunk = 0; chunk < 4; chunk++) {
        float z[16];
#pragma unroll
        for (int c = 0; c < 16; c++) {
            int ch = chunk * 16 + c;
            float4 a = cw4[ch * 2];
            float4 b = cw4[ch * 2 + 1];
            float v = fmaf(a.x, x0, fmaf(a.y, x1, fmaf(a.z, x2,
                      fmaf(a.w, x3, fmaf(b.x, x4, b.y)))));
            z[c] = fmaxf(v, 0.f);
        }
#pragma unroll
        for (int cc = 0; cc < 16; cc++) {
            int row = (hf * 16 + cc) * 16 + chunk * 4;
#pragma unroll
            for (int q = 0; q < 4; q++) {
                float4 ww = w4[row + q];
                o[cc] = fmaf(z[q*4+0], ww.x, fmaf(z[q*4+1], ww.y,
                        fmaf(z[q*4+2], ww.z, fmaf(z[q*4+3], ww.w, o[cc]))));
            }
        }
    }
    if (!act) {
#pragma unroll
        for (int c = 0; c < 16; c++) o[c] = 0.f;
    }
    if (act) {
        float4* dst = (float4*)&g_t2[(size_t)tok * 32 + hf * 16];
#pragma unroll
        for (int q = 0; q < 4; q++)
            dst[q] = make_float4(o[4*q], o[4*q+1], o[4*q+2], o[4*q+3]);
    }

    // BN2 stats: per-warp stride-33 transpose (16 tokens x 32 channels)
    float* tw = tile + w * 528;
    int tokin = (t >> 1) & 15;
#pragma unroll
    for (int c = 0; c < 16; c++)
        tw[tokin * 33 + hf * 16 + c] = o[c];
    __syncwarp();
    float s1 = 0.f, s2 = 0.f;
#pragma unroll
    for (int i = 0; i < 16; i++) {
        float v = tw[i * 33 + lane];
        s1 += v; s2 = fmaf(v, v, s2);
    }
    atomicAdd(&ssum[lane], s1);
    atomicAdd(&ssq[lane], s2);
    __syncthreads();
    if (t < 32) { red_f(&g_st2[t], ssum[t]); red_f(&g_st2[32 + t], ssq[t]); }
}

// ---- mlp3: warp per 8 tokens, lane = channel; butterfly norm ----
__global__ void mlp3_k(const float* __restrict__ g2,
                       const float* __restrict__ b2,
                       float* __restrict__ out,
                       int BK, float invN) {
#if __CUDA_ARCH__ >= 900
    cudaGridDependencySynchronize();
#endif
    __shared__ float sc[32], sh[32];
    int t = threadIdx.x, lane = t & 31, w = t >> 5;
    if (t < 32) {
        float m   = g_st2[t] * invN;
        float var = g_st2[32 + t] * invN - m * m;
        float s   = g2[t] * rsqrtf(var + EPS);
        sc[t] = s; sh[t] = b2[t] - m * s;
    }
    __syncthreads();
    float scl = sc[lane], shl = sh[lane];
    int tok0 = (blockIdx.x * 8 + w) * 8;
    float v[8];
#pragma unroll
    for (int tt = 0; tt < 8; tt++) {
        int tok = tok0 + tt;
        v[tt] = (tok < BK) ? g_t2[(size_t)tok * 32 + lane] : 0.f;
    }
#pragma unroll
    for (int tt = 0; tt < 8; tt++) {
        float x = fmaxf(fmaf(v[tt], scl, shl), 0.f);
        float n = x * x;
#pragma unroll
        for (int off = 16; off; off >>= 1)
            n += __shfl_xor_sync(0xffffffffu, n, off);
        float inv = 1.f / fmaxf(sqrtf(n), 1e-8f);
        int tok = tok0 + tt;
        if (tok < BK) out[(size_t)tok * 32 + lane] = x * inv;
    }
}

// ---- host: PDL-chained launches ----
static void launch_pdl(const void* fn, dim3 grid, dim3 block, void** args) {
    cudaLaunchConfig_t cfg = {};
    cfg.gridDim = grid; cfg.blockDim = block;
    cfg.dynamicSmemBytes = 0; cfg.stream = 0;
    cudaLaunchAttribute at[1];
    at[0].id = cudaLaunchAttributeProgrammaticStreamSerialization;
    at[0].val.programmaticStreamSerializationAllowed = 1;
    cfg.attrs = at; cfg.numAttrs = 1;
    cudaLaunchKernelExC(&cfg, fn, args);
}

extern "C" void kernel_launch(void* const* d_in, const int* in_sizes, int n_in,
                              void* d_out, int out_size) {
    const int*   labels = (const int*)  d_in[0];
    const float* fx     = (const float*)d_in[1];
    const float* fy     = (const float*)d_in[2];
    const int*   fidx   = (const int*)  d_in[3];
    int wi = 4;
    const int* nfp = nullptr;
    if (n_in >= 14) { nfp = (const int*)d_in[4]; wi = 6; }
    const float* cw = (const float*)d_in[wi + 0];
    const float* cb = (const float*)d_in[wi + 1];
    const float* g1 = (const float*)d_in[wi + 2];
    const float* b1 = (const float*)d_in[wi + 3];
    const float* lw = (const float*)d_in[wi + 4];
    const float* lb = (const float*)d_in[wi + 5];
    const float* g2 = (const float*)d_in[wi + 6];
    const float* b2 = (const float*)d_in[wi + 7];

    int B  = in_sizes[3];
    int Np = in_sizes[0];
    int P  = Np / B;
    int BK = out_size / 32;
    int K  = BK / B;
    int hh = (int)(sqrt((double)P) + 0.5);
    int ww = P / hh;
    float sx = 2.f / (float)(ww - 1);
    float sy = 2.f / (float)(hh - 1);
    float invN = 1.f / (float)BK;
    float* outp = (float*)d_out;

    bool fast = (hh * ww == P) && (hh % 4 == 0) && (P % CHUNK == 0) &&
                (K <= 2048) && (hh <= 1024) && (ww <= 1024);
    if (fast) {
        int cpb = P / CHUNK;
        pool_priv_k<<<B * cpb, PTHREADS, (size_t)K * 16>>>(labels, fx, fy, P, hh, K, cpb);
    } else {
        pool_gl_k<<<(Np + 255) / 256, 256>>>(labels, fx, fy, P, hh, K, Np);
    }

    {
        void* args[] = {(void*)&fidx, (void*)&nfp, (void*)&K, (void*)&BK,
                        (void*)&sx, (void*)&sy};
        launch_pdl((const void*)stats_k, dim3((BK + 127) / 128), dim3(128), args);
    }
    {
        void* args[] = {(void*)&cw, (void*)&cb, (void*)&g1, (void*)&b1,
                        (void*)&lw, (void*)&lb, (void*)&BK, (void*)&invN};
        launch_pdl((const void*)mlp12_k, dim3((BK + 63) / 64), dim3(128), args);
    }
    {
        void* args[] = {(void*)&g2, (void*)&b2, (void*)&outp, (void*)&BK, (void*)&invN};
        launch_pdl((const void*)mlp3_k, dim3((BK + 63) / 64), dim3(256), args);
    }
}